// round 1
// baseline (speedup 1.0000x reference)
#include <cuda_runtime.h>
#include <math.h>

#define Bb 2
#define Nn 2048
#define EMB 768
#define NH 12
#define DH 64
#define DEPTH 6
#define FF 3072
#define TOK (Bb * Nn)         // 4096
#define LN_EPS 1e-6f

// ---------------- scratch (static device globals; no allocation allowed) ----
__device__ float g_h[TOK * EMB];        // residual stream
__device__ float g_y[TOK * EMB];        // LN output
__device__ float g_qkv[TOK * 3 * EMB];  // qkv
__device__ float g_o[TOK * EMB];        // attention output
__device__ float g_mid[TOK * FF];       // FFN hidden

// ALiBi slopes for H=12 (8 + first-4-even-of-16 per reference formula)
__constant__ float c_slopes[NH] = {
    0.5f, 0.25f, 0.125f, 0.0625f, 0.03125f, 0.015625f, 0.0078125f, 0.00390625f,
    0.70710678118654752f, 0.35355339059327376f, 0.17677669529663688f,
    0.08838834764831844f};

// ---------------- copy x -> h ----------------------------------------------
__global__ void copy_kernel(const float* __restrict__ x) {
    int i = blockIdx.x * blockDim.x + threadIdx.x;
    if (i < TOK * EMB) g_h[i] = x[i];
}

// ---------------- LayerNorm -------------------------------------------------
__global__ void ln_kernel(const float* __restrict__ in,
                          const float* __restrict__ scale,
                          const float* __restrict__ bias,
                          float* __restrict__ out) {
    int row = blockIdx.x;
    const float* p = in + (size_t)row * EMB;
    float s = 0.f, ss = 0.f;
    for (int i = threadIdx.x; i < EMB; i += 256) {
        float v = p[i];
        s += v;
        ss += v * v;
    }
#pragma unroll
    for (int o = 16; o; o >>= 1) {
        s += __shfl_xor_sync(0xffffffffu, s, o);
        ss += __shfl_xor_sync(0xffffffffu, ss, o);
    }
    __shared__ float sh_s[8], sh_ss[8];
    int w = threadIdx.x >> 5, lane = threadIdx.x & 31;
    if (lane == 0) { sh_s[w] = s; sh_ss[w] = ss; }
    __syncthreads();
    if (threadIdx.x < 32) {
        s = (lane < 8) ? sh_s[lane] : 0.f;
        ss = (lane < 8) ? sh_ss[lane] : 0.f;
#pragma unroll
        for (int o = 4; o; o >>= 1) {
            s += __shfl_xor_sync(0xffffffffu, s, o);
            ss += __shfl_xor_sync(0xffffffffu, ss, o);
        }
        if (lane == 0) { sh_s[0] = s; sh_ss[0] = ss; }
    }
    __syncthreads();
    float mean = sh_s[0] * (1.0f / EMB);
    float var = sh_ss[0] * (1.0f / EMB) - mean * mean;
    float inv = rsqrtf(var + LN_EPS);
    float* q = out + (size_t)row * EMB;
    for (int i = threadIdx.x; i < EMB; i += 256)
        q[i] = (p[i] - mean) * inv * scale[i] + bias[i];
}

// ---------------- GEMM: C[M,N] = A[M,K] @ W[K,N]  (+bias, +gelu, +=C) -------
#define FLAG_BIAS 1
#define FLAG_GELU 2
#define FLAG_ADD 4

__device__ __forceinline__ float gelu_tanh(float x) {
    const float k0 = 0.7978845608028654f;  // sqrt(2/pi)
    return 0.5f * x * (1.0f + tanhf(k0 * (x + 0.044715f * x * x * x)));
}

__global__ __launch_bounds__(256) void gemm_kernel(
    const float* __restrict__ A, const float* __restrict__ W,
    const float* __restrict__ bias, float* __restrict__ C, int M, int K,
    int Nout, int flags) {
    __shared__ float As[16][128];
    __shared__ float Bs[16][128];

    int tid = threadIdx.x;
    int bm = blockIdx.y * 128;
    int bn = blockIdx.x * 128;
    int tr = tid >> 4;         // 0..15
    int tc = tid & 15;         // 0..15

    int arow = tid >> 2;            // 0..63
    int acol4 = (tid & 3) * 4;      // 0,4,8,12
    int brow = tid >> 5;            // 0..7
    int bcol4 = (tid & 31) * 4;     // 0..124

    float acc[8][8];
#pragma unroll
    for (int i = 0; i < 8; i++)
#pragma unroll
        for (int j = 0; j < 8; j++) acc[i][j] = 0.f;

    for (int k0 = 0; k0 < K; k0 += 16) {
#pragma unroll
        for (int r = 0; r < 2; r++) {
            float4 v = *(const float4*)(A + (size_t)(bm + arow + r * 64) * K +
                                        k0 + acol4);
            As[acol4 + 0][arow + r * 64] = v.x;
            As[acol4 + 1][arow + r * 64] = v.y;
            As[acol4 + 2][arow + r * 64] = v.z;
            As[acol4 + 3][arow + r * 64] = v.w;
        }
#pragma unroll
        for (int r = 0; r < 2; r++) {
            float4 v = *(const float4*)(W + (size_t)(k0 + brow + r * 8) * Nout +
                                        bn + bcol4);
            *(float4*)&Bs[brow + r * 8][bcol4] = v;
        }
        __syncthreads();
#pragma unroll
        for (int k = 0; k < 16; k++) {
            float a[8], b[8];
            *(float4*)(a + 0) = *(float4*)&As[k][tr * 4];
            *(float4*)(a + 4) = *(float4*)&As[k][64 + tr * 4];
            *(float4*)(b + 0) = *(float4*)&Bs[k][tc * 4];
            *(float4*)(b + 4) = *(float4*)&Bs[k][64 + tc * 4];
#pragma unroll
            for (int i = 0; i < 8; i++)
#pragma unroll
                for (int j = 0; j < 8; j++) acc[i][j] = fmaf(a[i], b[j], acc[i][j]);
        }
        __syncthreads();
    }

#pragma unroll
    for (int ri = 0; ri < 2; ri++) {
#pragma unroll
        for (int i = 0; i < 4; i++) {
            int m = bm + ri * 64 + tr * 4 + i;
#pragma unroll
            for (int ci = 0; ci < 2; ci++) {
#pragma unroll
                for (int j = 0; j < 4; j++) {
                    int n = bn + ci * 64 + tc * 4 + j;
                    float c = acc[ri * 4 + i][ci * 4 + j];
                    if (flags & FLAG_BIAS) c += bias[n];
                    if (flags & FLAG_GELU) c = gelu_tanh(c);
                    size_t off = (size_t)m * Nout + n;
                    if (flags & FLAG_ADD)
                        C[off] += c;
                    else
                        C[off] = c;
                }
            }
        }
    }
}

// ---------------- flash attention (causal + ALiBi) --------------------------
// grid: (N/64 q-tiles, B*H); block 128 threads = 64 queries x 2 dim-halves
__global__ __launch_bounds__(128) void attn_kernel(
    const float* __restrict__ qkv, float* __restrict__ out) {
    __shared__ float Qs[64][65];
    __shared__ float Ks[32][65];
    __shared__ float Vs[32][65];
    __shared__ float Ss[64][33];

    int qt = blockIdx.x;
    int bh = blockIdx.y;
    int b = bh / NH, h = bh % NH;
    int t = threadIdx.x;
    int q = t >> 1;
    int half = t & 1;
    int dstart = half * 32;
    int nq = qt * 64 + q;
    float slope = c_slopes[h];
    const float scale = 0.125f;  // 64^-0.5

    // load Q tile (scaled)
    for (int i = 0; i < 32; i++) {
        int idx = t + i * 128;
        int row = idx >> 6, d = idx & 63;
        Qs[row][d] =
            qkv[((size_t)(b * Nn + qt * 64 + row) * (3 * EMB)) + h * DH + d] *
            scale;
    }

    float m = -1e30f, l = 0.f;
    float acc[32];
#pragma unroll
    for (int d = 0; d < 32; d++) acc[d] = 0.f;

    int kt_end = 2 * qt + 1;
    for (int kt = 0; kt <= kt_end; kt++) {
        __syncthreads();
        // load K/V tile (32 keys x 64 dims)
        for (int i = 0; i < 16; i++) {
            int idx = t + i * 128;
            int row = idx >> 6, d = idx & 63;
            size_t base = (size_t)(b * Nn + kt * 32 + row) * (3 * EMB) + h * DH + d;
            Ks[row][d] = qkv[base + EMB];
            Vs[row][d] = qkv[base + 2 * EMB];
        }
        __syncthreads();

        // scores for my query, my 16 keys
        for (int jj = 0; jj < 16; jj++) {
            int j = half * 16 + jj;
            int nk = kt * 32 + j;
            float s;
            if (nk > nq) {
                s = -1e30f;
            } else {
                s = 0.f;
#pragma unroll
                for (int d = 0; d < 64; d++) s = fmaf(Qs[q][d], Ks[j][d], s);
                s += slope * (float)nk;
            }
            Ss[q][j] = s;
        }
        __syncthreads();

        // online softmax over the 32-key tile (both threads of pair replicate)
        float tmax = -1e30f;
#pragma unroll
        for (int j = 0; j < 32; j++) tmax = fmaxf(tmax, Ss[q][j]);
        float newm = fmaxf(m, tmax);
        float corr = expf(m - newm);
        m = newm;
        l *= corr;
#pragma unroll
        for (int d = 0; d < 32; d++) acc[d] *= corr;
        for (int j = 0; j < 32; j++) {
            float p = expf(Ss[q][j] - newm);
            l += p;
#pragma unroll
            for (int d = 0; d < 32; d++)
                acc[d] = fmaf(p, Vs[j][dstart + d], acc[d]);
        }
    }

    float invl = 1.0f / l;
    float* op = out + (size_t)(b * Nn + nq) * EMB + h * DH + dstart;
#pragma unroll
    for (int d = 0; d < 32; d++) op[d] = acc[d] * invl;
}

// ---------------- host orchestration ----------------------------------------
extern "C" void kernel_launch(void* const* d_in, const int* in_sizes, int n_in,
                              void* d_out, int out_size) {
    const float* x = (const float*)d_in[0];
    const float* wqkv = (const float*)d_in[1];
    const float* bqkv = (const float*)d_in[2];
    const float* wo = (const float*)d_in[3];
    const float* bo = (const float*)d_in[4];
    const float* ln1s = (const float*)d_in[5];
    const float* ln1b = (const float*)d_in[6];
    const float* ln2s = (const float*)d_in[7];
    const float* ln2b = (const float*)d_in[8];
    const float* w1 = (const float*)d_in[9];
    const float* w2 = (const float*)d_in[10];
    const float* lnfs = (const float*)d_in[11];
    const float* lnfb = (const float*)d_in[12];
    float* out = (float*)d_out;

    float *p_h, *p_y, *p_qkv, *p_o, *p_mid;
    cudaGetSymbolAddress((void**)&p_h, g_h);
    cudaGetSymbolAddress((void**)&p_y, g_y);
    cudaGetSymbolAddress((void**)&p_qkv, g_qkv);
    cudaGetSymbolAddress((void**)&p_o, g_o);
    cudaGetSymbolAddress((void**)&p_mid, g_mid);

    copy_kernel<<<(TOK * EMB + 255) / 256, 256>>>(x);

    for (int L = 0; L < DEPTH; L++) {
        // y = LN1(h)
        ln_kernel<<<TOK, 256>>>(p_h, ln1s + L * EMB, ln1b + L * EMB, p_y);
        // qkv = y @ Wqkv + bqkv
        {
            dim3 grid(3 * EMB / 128, TOK / 128);
            gemm_kernel<<<grid, 256>>>(p_y, wqkv + (size_t)L * EMB * 3 * EMB,
                                       bqkv + L * 3 * EMB, p_qkv, TOK, EMB,
                                       3 * EMB, FLAG_BIAS);
        }
        // attention
        {
            dim3 grid(Nn / 64, Bb * NH);
            attn_kernel<<<grid, 128>>>(p_qkv, p_o);
        }
        // h += o @ Wo + bo
        {
            dim3 grid(EMB / 128, TOK / 128);
            gemm_kernel<<<grid, 256>>>(p_o, wo + (size_t)L * EMB * EMB,
                                       bo + L * EMB, p_h, TOK, EMB, EMB,
                                       FLAG_BIAS | FLAG_ADD);
        }
        // y = LN2(h)
        ln_kernel<<<TOK, 256>>>(p_h, ln2s + L * EMB, ln2b + L * EMB, p_y);
        // mid = gelu(y @ W1)
        {
            dim3 grid(FF / 128, TOK / 128);
            gemm_kernel<<<grid, 256>>>(p_y, w1 + (size_t)L * EMB * FF, nullptr,
                                       p_mid, TOK, EMB, FF, FLAG_GELU);
        }
        // h += mid @ W2
        {
            dim3 grid(EMB / 128, TOK / 128);
            gemm_kernel<<<grid, 256>>>(p_mid, w2 + (size_t)L * FF * EMB,
                                       nullptr, p_h, TOK, FF, EMB, FLAG_ADD);
        }
    }

    // out = LN_f(h)
    ln_kernel<<<TOK, 256>>>(p_h, lnfs, lnfb, out);
}

// round 2
// speedup vs baseline: 1.2962x; 1.2962x over previous
#include <cuda_runtime.h>
#include <math.h>
#include <stdint.h>

#define Bb 2
#define Nn 2048
#define EMB 768
#define NH 12
#define DH 64
#define DEPTH 6
#define FF 3072
#define TOK (Bb * Nn)         // 4096
#define LN_EPS 1e-6f

// ---------------- scratch (static device globals; no allocation allowed) ----
__device__ float g_h[TOK * EMB];        // residual stream
__device__ float g_y[TOK * EMB];        // LN output (tf32-rounded)
__device__ float g_qkv[TOK * 3 * EMB];  // qkv (full fp32)
__device__ float g_o[TOK * EMB];        // attention output (tf32-rounded)
__device__ float g_mid[TOK * FF];       // FFN hidden (tf32-rounded)
// tf32-rounded weights
__device__ float g_wqkv[DEPTH * EMB * 3 * EMB];
__device__ float g_wo[DEPTH * EMB * EMB];
__device__ float g_w1[DEPTH * EMB * FF];
__device__ float g_w2[DEPTH * FF * EMB];

// ALiBi slopes for H=12
__constant__ float c_slopes[NH] = {
    0.5f, 0.25f, 0.125f, 0.0625f, 0.03125f, 0.015625f, 0.0078125f, 0.00390625f,
    0.70710678118654752f, 0.35355339059327376f, 0.17677669529663688f,
    0.08838834764831844f};

__device__ __forceinline__ float rna_tf32(float x) {
    uint32_t u;
    asm("cvt.rna.tf32.f32 %0, %1;" : "=r"(u) : "f"(x));
    return __uint_as_float(u);
}

// ---------------- copy x -> h ----------------------------------------------
__global__ void copy_kernel(const float* __restrict__ x) {
    int i = blockIdx.x * blockDim.x + threadIdx.x;
    if (i < TOK * EMB) g_h[i] = x[i];
}

// ---------------- weight tf32 pre-rounding ----------------------------------
__global__ void round_kernel(const float4* __restrict__ in,
                             float4* __restrict__ out, int n4) {
    int i = blockIdx.x * blockDim.x + threadIdx.x;
    if (i < n4) {
        float4 v = in[i];
        v.x = rna_tf32(v.x);
        v.y = rna_tf32(v.y);
        v.z = rna_tf32(v.z);
        v.w = rna_tf32(v.w);
        out[i] = v;
    }
}

// ---------------- LayerNorm -------------------------------------------------
__global__ void ln_kernel(const float* __restrict__ in,
                          const float* __restrict__ scale,
                          const float* __restrict__ bias,
                          float* __restrict__ out, int do_rna) {
    int row = blockIdx.x;
    const float* p = in + (size_t)row * EMB;
    float s = 0.f, ss = 0.f;
    for (int i = threadIdx.x; i < EMB; i += 256) {
        float v = p[i];
        s += v;
        ss += v * v;
    }
#pragma unroll
    for (int o = 16; o; o >>= 1) {
        s += __shfl_xor_sync(0xffffffffu, s, o);
        ss += __shfl_xor_sync(0xffffffffu, ss, o);
    }
    __shared__ float sh_s[8], sh_ss[8];
    int w = threadIdx.x >> 5, lane = threadIdx.x & 31;
    if (lane == 0) { sh_s[w] = s; sh_ss[w] = ss; }
    __syncthreads();
    if (threadIdx.x < 32) {
        s = (lane < 8) ? sh_s[lane] : 0.f;
        ss = (lane < 8) ? sh_ss[lane] : 0.f;
#pragma unroll
        for (int o = 4; o; o >>= 1) {
            s += __shfl_xor_sync(0xffffffffu, s, o);
            ss += __shfl_xor_sync(0xffffffffu, ss, o);
        }
        if (lane == 0) { sh_s[0] = s; sh_ss[0] = ss; }
    }
    __syncthreads();
    float mean = sh_s[0] * (1.0f / EMB);
    float var = sh_ss[0] * (1.0f / EMB) - mean * mean;
    float inv = rsqrtf(var + LN_EPS);
    float* q = out + (size_t)row * EMB;
    for (int i = threadIdx.x; i < EMB; i += 256) {
        float v = (p[i] - mean) * inv * scale[i] + bias[i];
        q[i] = do_rna ? rna_tf32(v) : v;
    }
}

// ---------------- tf32 tensor-core GEMM -------------------------------------
// C[M,N] = A[M,K] @ W[K,N]  (+bias, +gelu, +rna, +=C)
#define FLAG_BIAS 1
#define FLAG_GELU 2
#define FLAG_ADD 4
#define FLAG_RNA 8

#define KT 32
#define AS_PAD 36
#define BS_PAD 132
#define AS_TILE (128 * AS_PAD)  // floats per A buffer
#define BS_TILE (32 * BS_PAD)   // floats per B buffer
#define GEMM_SMEM_BYTES ((2 * AS_TILE + 2 * BS_TILE) * 4)

__device__ __forceinline__ float gelu_tanh(float x) {
    const float k0 = 0.7978845608028654f;  // sqrt(2/pi)
    return 0.5f * x * (1.0f + tanhf(k0 * (x + 0.044715f * x * x * x)));
}

__device__ __forceinline__ void cp16(uint32_t dst, const void* src) {
    asm volatile("cp.async.ca.shared.global [%0], [%1], 16;" ::"r"(dst),
                 "l"(src));
}

#define MMA_TF32(d, a, b)                                                     \
    asm volatile(                                                             \
        "mma.sync.aligned.m16n8k8.row.col.f32.tf32.tf32.f32 "                 \
        "{%0,%1,%2,%3},{%4,%5,%6,%7},{%8,%9},{%0,%1,%2,%3};"                  \
        : "+f"(d[0]), "+f"(d[1]), "+f"(d[2]), "+f"(d[3])                      \
        : "r"(a[0]), "r"(a[1]), "r"(a[2]), "r"(a[3]), "r"(b[0]), "r"(b[1]))

__global__ __launch_bounds__(256, 2) void gemm_tf32(
    const float* __restrict__ A, const float* __restrict__ W,
    const float* __restrict__ bias, float* __restrict__ C, int M, int K,
    int Nout, int flags) {
    extern __shared__ float smem[];
    float* sA = smem;                 // [2][128][36]
    float* sB = smem + 2 * AS_TILE;   // [2][32][132]

    int tid = threadIdx.x;
    int bm = blockIdx.y * 128;
    int bn = blockIdx.x * 128;
    int warp = tid >> 5, lane = tid & 31;
    int wm = warp >> 2, wn = warp & 3;
    int r = lane >> 2, kq = lane & 3;

    // staging indices: A 128x32 floats (2 threads/row, 4x16B each),
    //                  B 32x128 floats (8 threads/row, 4x16B each)
    int a_row = tid >> 1, a_col = (tid & 1) * 16;
    int b_row = tid >> 3, b_col = (tid & 7) * 16;
    const float* Ag = A + (size_t)(bm + a_row) * K + a_col;
    const float* Bg = W + (size_t)b_row * Nout + bn + b_col;
    uint32_t sa_base =
        (uint32_t)__cvta_generic_to_shared(sA + a_row * AS_PAD + a_col);
    uint32_t sb_base =
        (uint32_t)__cvta_generic_to_shared(sB + b_row * BS_PAD + b_col);

    float acc[4][4][4];
#pragma unroll
    for (int i = 0; i < 4; i++)
#pragma unroll
        for (int j = 0; j < 4; j++)
#pragma unroll
            for (int c = 0; c < 4; c++) acc[i][j][c] = 0.f;

    int ntiles = K / KT;

    // prologue: tile 0 -> buf 0
    {
        const float* ga = Ag;
        const float* gb = Bg;
#pragma unroll
        for (int j = 0; j < 4; j++) cp16(sa_base + j * 16, ga + j * 4);
#pragma unroll
        for (int j = 0; j < 4; j++) cp16(sb_base + j * 16, gb + j * 4);
        asm volatile("cp.async.commit_group;");
    }

    int buf = 0;
    for (int t = 0; t < ntiles; t++) {
        if (t + 1 < ntiles) {
            int k0 = (t + 1) * KT;
            int nb = buf ^ 1;
            const float* ga = Ag + k0;
            const float* gb = Bg + (size_t)k0 * Nout;
            uint32_t sa = sa_base + nb * AS_TILE * 4;
            uint32_t sb = sb_base + nb * BS_TILE * 4;
#pragma unroll
            for (int j = 0; j < 4; j++) cp16(sa + j * 16, ga + j * 4);
#pragma unroll
            for (int j = 0; j < 4; j++) cp16(sb + j * 16, gb + j * 4);
            asm volatile("cp.async.commit_group;");
            asm volatile("cp.async.wait_group 1;");
        } else {
            asm volatile("cp.async.wait_group 0;");
        }
        __syncthreads();

        const uint32_t* uA = (const uint32_t*)(sA + buf * AS_TILE);
        const uint32_t* uB = (const uint32_t*)(sB + buf * BS_TILE);
#pragma unroll
        for (int ks = 0; ks < 4; ks++) {
            int kb = ks * 8;
            uint32_t af[4][4], bf[4][2];
#pragma unroll
            for (int mf = 0; mf < 4; mf++) {
                const uint32_t* p =
                    uA + (wm * 64 + mf * 16 + r) * AS_PAD + kb + kq;
                af[mf][0] = p[0];
                af[mf][1] = p[8 * AS_PAD];
                af[mf][2] = p[4];
                af[mf][3] = p[8 * AS_PAD + 4];
            }
#pragma unroll
            for (int nf = 0; nf < 4; nf++) {
                const uint32_t* p =
                    uB + (kb + kq) * BS_PAD + wn * 32 + nf * 8 + r;
                bf[nf][0] = p[0];
                bf[nf][1] = p[4 * BS_PAD];
            }
#pragma unroll
            for (int mf = 0; mf < 4; mf++)
#pragma unroll
                for (int nf = 0; nf < 4; nf++)
                    MMA_TF32(acc[mf][nf], af[mf], bf[nf]);
        }
        __syncthreads();
        buf ^= 1;
    }

    // epilogue
#pragma unroll
    for (int mf = 0; mf < 4; mf++) {
#pragma unroll
        for (int nf = 0; nf < 4; nf++) {
            int n0 = bn + wn * 32 + nf * 8 + kq * 2;
#pragma unroll
            for (int half = 0; half < 2; half++) {
                int m0 = bm + wm * 64 + mf * 16 + r + half * 8;
                float2 v;
                v.x = acc[mf][nf][half * 2 + 0];
                v.y = acc[mf][nf][half * 2 + 1];
                if (flags & FLAG_BIAS) {
                    v.x += bias[n0];
                    v.y += bias[n0 + 1];
                }
                if (flags & FLAG_GELU) {
                    v.x = gelu_tanh(v.x);
                    v.y = gelu_tanh(v.y);
                }
                if (flags & FLAG_RNA) {
                    v.x = rna_tf32(v.x);
                    v.y = rna_tf32(v.y);
                }
                float2* dst = (float2*)&C[(size_t)m0 * Nout + n0];
                if (flags & FLAG_ADD) {
                    float2 old = *dst;
                    v.x += old.x;
                    v.y += old.y;
                }
                *dst = v;
            }
        }
    }
}

// ---------------- flash attention (causal + ALiBi) --------------------------
__global__ __launch_bounds__(128) void attn_kernel(
    const float* __restrict__ qkv, float* __restrict__ out) {
    __shared__ float Qs[64][65];
    __shared__ float Ks[32][65];
    __shared__ float Vs[32][65];
    __shared__ float Ss[64][33];

    int qt = blockIdx.x;
    int bh = blockIdx.y;
    int b = bh / NH, h = bh % NH;
    int t = threadIdx.x;
    int q = t >> 1;
    int half = t & 1;
    int dstart = half * 32;
    int nq = qt * 64 + q;
    float slope = c_slopes[h];
    const float scale = 0.125f;  // 64^-0.5

    for (int i = 0; i < 32; i++) {
        int idx = t + i * 128;
        int row = idx >> 6, d = idx & 63;
        Qs[row][d] =
            qkv[((size_t)(b * Nn + qt * 64 + row) * (3 * EMB)) + h * DH + d] *
            scale;
    }

    float m = -1e30f, l = 0.f;
    float acc[32];
#pragma unroll
    for (int d = 0; d < 32; d++) acc[d] = 0.f;

    int kt_end = 2 * qt + 1;
    for (int kt = 0; kt <= kt_end; kt++) {
        __syncthreads();
        for (int i = 0; i < 16; i++) {
            int idx = t + i * 128;
            int row = idx >> 6, d = idx & 63;
            size_t base =
                (size_t)(b * Nn + kt * 32 + row) * (3 * EMB) + h * DH + d;
            Ks[row][d] = qkv[base + EMB];
            Vs[row][d] = qkv[base + 2 * EMB];
        }
        __syncthreads();

        for (int jj = 0; jj < 16; jj++) {
            int j = half * 16 + jj;
            int nk = kt * 32 + j;
            float s;
            if (nk > nq) {
                s = -1e30f;
            } else {
                s = 0.f;
#pragma unroll
                for (int d = 0; d < 64; d++) s = fmaf(Qs[q][d], Ks[j][d], s);
                s += slope * (float)nk;
            }
            Ss[q][j] = s;
        }
        __syncthreads();

        float tmax = -1e30f;
#pragma unroll
        for (int j = 0; j < 32; j++) tmax = fmaxf(tmax, Ss[q][j]);
        float newm = fmaxf(m, tmax);
        float corr = expf(m - newm);
        m = newm;
        l *= corr;
#pragma unroll
        for (int d = 0; d < 32; d++) acc[d] *= corr;
        for (int j = 0; j < 32; j++) {
            float p = expf(Ss[q][j] - newm);
            l += p;
#pragma unroll
            for (int d = 0; d < 32; d++)
                acc[d] = fmaf(p, Vs[j][dstart + d], acc[d]);
        }
    }

    float invl = 1.0f / l;
    float* op = out + (size_t)(b * Nn + nq) * EMB + h * DH + dstart;
#pragma unroll
    for (int d = 0; d < 32; d++) op[d] = rna_tf32(acc[d] * invl);
}

// ---------------- host orchestration ----------------------------------------
extern "C" void kernel_launch(void* const* d_in, const int* in_sizes, int n_in,
                              void* d_out, int out_size) {
    const float* x = (const float*)d_in[0];
    const float* wqkv = (const float*)d_in[1];
    const float* bqkv = (const float*)d_in[2];
    const float* wo = (const float*)d_in[3];
    const float* bo = (const float*)d_in[4];
    const float* ln1s = (const float*)d_in[5];
    const float* ln1b = (const float*)d_in[6];
    const float* ln2s = (const float*)d_in[7];
    const float* ln2b = (const float*)d_in[8];
    const float* w1 = (const float*)d_in[9];
    const float* w2 = (const float*)d_in[10];
    const float* lnfs = (const float*)d_in[11];
    const float* lnfb = (const float*)d_in[12];
    float* out = (float*)d_out;

    float *p_h, *p_y, *p_qkv, *p_o, *p_mid;
    float *p_wqkv, *p_wo, *p_w1, *p_w2;
    cudaGetSymbolAddress((void**)&p_h, g_h);
    cudaGetSymbolAddress((void**)&p_y, g_y);
    cudaGetSymbolAddress((void**)&p_qkv, g_qkv);
    cudaGetSymbolAddress((void**)&p_o, g_o);
    cudaGetSymbolAddress((void**)&p_mid, g_mid);
    cudaGetSymbolAddress((void**)&p_wqkv, g_wqkv);
    cudaGetSymbolAddress((void**)&p_wo, g_wo);
    cudaGetSymbolAddress((void**)&p_w1, g_w1);
    cudaGetSymbolAddress((void**)&p_w2, g_w2);

    cudaFuncSetAttribute(gemm_tf32, cudaFuncAttributeMaxDynamicSharedMemorySize,
                         GEMM_SMEM_BYTES);

    copy_kernel<<<(TOK * EMB + 255) / 256, 256>>>(x);

    // pre-round all weights to tf32
    {
        int n4 = DEPTH * EMB * 3 * EMB / 4;
        round_kernel<<<(n4 + 255) / 256, 256>>>((const float4*)wqkv,
                                                (float4*)p_wqkv, n4);
        n4 = DEPTH * EMB * EMB / 4;
        round_kernel<<<(n4 + 255) / 256, 256>>>((const float4*)wo,
                                                (float4*)p_wo, n4);
        n4 = DEPTH * EMB * FF / 4;
        round_kernel<<<(n4 + 255) / 256, 256>>>((const float4*)w1,
                                                (float4*)p_w1, n4);
        n4 = DEPTH * FF * EMB / 4;
        round_kernel<<<(n4 + 255) / 256, 256>>>((const float4*)w2,
                                                (float4*)p_w2, n4);
    }

    for (int L = 0; L < DEPTH; L++) {
        // y = rna(LN1(h))
        ln_kernel<<<TOK, 256>>>(p_h, ln1s + L * EMB, ln1b + L * EMB, p_y, 1);
        // qkv = y @ Wqkv + bqkv (full fp32 result for attention)
        {
            dim3 grid(3 * EMB / 128, TOK / 128);
            gemm_tf32<<<grid, 256, GEMM_SMEM_BYTES>>>(
                p_y, p_wqkv + (size_t)L * EMB * 3 * EMB, bqkv + L * 3 * EMB,
                p_qkv, TOK, EMB, 3 * EMB, FLAG_BIAS);
        }
        // attention (fp32, output rna'd)
        {
            dim3 grid(Nn / 64, Bb * NH);
            attn_kernel<<<grid, 128>>>(p_qkv, p_o);
        }
        // h += o @ Wo + bo
        {
            dim3 grid(EMB / 128, TOK / 128);
            gemm_tf32<<<grid, 256, GEMM_SMEM_BYTES>>>(
                p_o, p_wo + (size_t)L * EMB * EMB, bo + L * EMB, p_h, TOK, EMB,
                EMB, FLAG_BIAS | FLAG_ADD);
        }
        // y = rna(LN2(h))
        ln_kernel<<<TOK, 256>>>(p_h, ln2s + L * EMB, ln2b + L * EMB, p_y, 1);
        // mid = rna(gelu(y @ W1))
        {
            dim3 grid(FF / 128, TOK / 128);
            gemm_tf32<<<grid, 256, GEMM_SMEM_BYTES>>>(
                p_y, p_w1 + (size_t)L * EMB * FF, nullptr, p_mid, TOK, EMB, FF,
                FLAG_GELU | FLAG_RNA);
        }
        // h += mid @ W2
        {
            dim3 grid(EMB / 128, TOK / 128);
            gemm_tf32<<<grid, 256, GEMM_SMEM_BYTES>>>(
                p_mid, p_w2 + (size_t)L * FF * EMB, nullptr, p_h, TOK, FF, EMB,
                FLAG_ADD);
        }
    }

    // out = LN_f(h) (no rounding)
    ln_kernel<<<TOK, 256>>>(p_h, lnfs, lnfb, out, 0);
}

// round 5
// speedup vs baseline: 1.3487x; 1.0405x over previous
#include <cuda_runtime.h>
#include <math.h>
#include <stdint.h>

#define Bb 2
#define Nn 2048
#define EMB 768
#define NH 12
#define DH 64
#define DEPTH 6
#define FF 3072
#define TOK (Bb * Nn)  // 4096
#define LN_EPS 1e-6f

// ---------------- scratch (static device globals) ---------------------------
__device__ float g_h[TOK * EMB];
__device__ float g_y[TOK * EMB];
__device__ float g_qkv[TOK * 3 * EMB];
__device__ float g_o[TOK * EMB];
__device__ float g_mid[TOK * FF];
// transposed + tf32-rounded weights ([Nout][K], K-major rows)
__device__ float g_wqkv[DEPTH * EMB * 3 * EMB];
__device__ float g_wo[DEPTH * EMB * EMB];
__device__ float g_w1[DEPTH * EMB * FF];
__device__ float g_w2[DEPTH * FF * EMB];

__constant__ float c_slopes[NH] = {
    0.5f, 0.25f, 0.125f, 0.0625f, 0.03125f, 0.015625f, 0.0078125f, 0.00390625f,
    0.70710678118654752f, 0.35355339059327376f, 0.17677669529663688f,
    0.08838834764831844f};

__device__ __forceinline__ float rna_tf32(float x) {
    uint32_t u;
    asm("cvt.rna.tf32.f32 %0, %1;" : "=r"(u) : "f"(x));
    return __uint_as_float(u);
}

__device__ __forceinline__ void cp16(uint32_t dst, const void* src) {
    asm volatile("cp.async.ca.shared.global [%0], [%1], 16;" ::"r"(dst),
                 "l"(src));
}

#define MMA_TF32(d, a, b)                                                     \
    asm volatile(                                                             \
        "mma.sync.aligned.m16n8k8.row.col.f32.tf32.tf32.f32 "                 \
        "{%0,%1,%2,%3},{%4,%5,%6,%7},{%8,%9},{%0,%1,%2,%3};"                  \
        : "+f"(d[0]), "+f"(d[1]), "+f"(d[2]), "+f"(d[3])                      \
        : "r"(a[0]), "r"(a[1]), "r"(a[2]), "r"(a[3]), "r"(b[0]), "r"(b[1]))

#define LDSM_X4(r0, r1, r2, r3, addr)                                        \
    asm volatile(                                                            \
        "ldmatrix.sync.aligned.m8n8.x4.shared.b16 {%0,%1,%2,%3}, [%4];"      \
        : "=r"(r0), "=r"(r1), "=r"(r2), "=r"(r3)                             \
        : "r"(addr))

#define LDSM_X2(r0, r1, addr)                                                \
    asm volatile("ldmatrix.sync.aligned.m8n8.x2.shared.b16 {%0,%1}, [%2];"   \
                 : "=r"(r0), "=r"(r1)                                        \
                 : "r"(addr))

// ---------------- copy x -> h ------------------------------------------------
__global__ void copy_kernel(const float* __restrict__ x) {
    int i = blockIdx.x * blockDim.x + threadIdx.x;
    if (i < TOK * EMB) g_h[i] = x[i];
}

// ---------------- transpose + tf32 round: W[K][N] -> Wt[N][K] ---------------
__global__ void transpose_round(const float* __restrict__ W,
                                float* __restrict__ Wt, int K, int N) {
    __shared__ float tile[32][33];
    const float* Wl = W + (size_t)blockIdx.z * K * N;
    float* Wtl = Wt + (size_t)blockIdx.z * K * N;
    int bn = blockIdx.x * 32, bk = blockIdx.y * 32;
    int tx = threadIdx.x, ty = threadIdx.y;
#pragma unroll
    for (int i = 0; i < 32; i += 8)
        tile[ty + i][tx] = Wl[(size_t)(bk + ty + i) * N + bn + tx];
    __syncthreads();
#pragma unroll
    for (int i = 0; i < 32; i += 8)
        Wtl[(size_t)(bn + ty + i) * K + bk + tx] = rna_tf32(tile[tx][ty + i]);
}

// ---------------- LayerNorm --------------------------------------------------
__global__ void ln_kernel(const float* __restrict__ in,
                          const float* __restrict__ scale,
                          const float* __restrict__ bias,
                          float* __restrict__ out, int do_rna) {
    int row = blockIdx.x;
    const float* p = in + (size_t)row * EMB;
    float s = 0.f, ss = 0.f;
    for (int i = threadIdx.x; i < EMB; i += 256) {
        float v = p[i];
        s += v;
        ss += v * v;
    }
#pragma unroll
    for (int o = 16; o; o >>= 1) {
        s += __shfl_xor_sync(0xffffffffu, s, o);
        ss += __shfl_xor_sync(0xffffffffu, ss, o);
    }
    __shared__ float sh_s[8], sh_ss[8];
    int w = threadIdx.x >> 5, lane = threadIdx.x & 31;
    if (lane == 0) { sh_s[w] = s; sh_ss[w] = ss; }
    __syncthreads();
    if (threadIdx.x < 32) {
        s = (lane < 8) ? sh_s[lane] : 0.f;
        ss = (lane < 8) ? sh_ss[lane] : 0.f;
#pragma unroll
        for (int o = 4; o; o >>= 1) {
            s += __shfl_xor_sync(0xffffffffu, s, o);
            ss += __shfl_xor_sync(0xffffffffu, ss, o);
        }
        if (lane == 0) { sh_s[0] = s; sh_ss[0] = ss; }
    }
    __syncthreads();
    float mean = sh_s[0] * (1.0f / EMB);
    float var = sh_ss[0] * (1.0f / EMB) - mean * mean;
    float inv = rsqrtf(var + LN_EPS);
    float* q = out + (size_t)row * EMB;
    for (int i = threadIdx.x; i < EMB; i += 256) {
        float v = (p[i] - mean) * inv * scale[i] + bias[i];
        q[i] = do_rna ? rna_tf32(v) : v;
    }
}

// ---------------- tf32 mma.sync GEMM w/ ldmatrix -----------------------------
// C[M,Nout] = A[M,K] @ Wt[Nout,K]^T  (+bias, +gelu, +rna, +=C)
// block 128x128, 8 warps (2m x 4n), warp tile 64x32, K-tile 32, 3-stage ring.
#define FLAG_BIAS 1
#define FLAG_GELU 2
#define FLAG_ADD 4
#define FLAG_RNA 8

#define STAGES 3
#define STAGE_BYTES 32768  // A 16KB + B 16KB (128 rows x 128B each)
#define GEMM_SMEM (STAGES * STAGE_BYTES)

__device__ __forceinline__ float gelu_tanh(float x) {
    const float k0 = 0.7978845608028654f;
    return 0.5f * x * (1.0f + tanhf(k0 * (x + 0.044715f * x * x * x)));
}

__global__ __launch_bounds__(256, 2) void gemm_tc(
    const float* __restrict__ A, const float* __restrict__ Wt,
    const float* __restrict__ bias, float* __restrict__ C, int K, int Nout,
    int flags) {
    extern __shared__ char smem[];
    const uint32_t sb = (uint32_t)__cvta_generic_to_shared(smem);
    const int tid = threadIdx.x;
    const int warp = tid >> 5, lane = tid & 31;
    const int wm = warp >> 2, wn = warp & 3;  // 2 x 4 warps
    const int bm = blockIdx.y * 128, bn = blockIdx.x * 128;

    // ---- staging setup: thread -> (row, 4 chunks of 16B) ----
    const int srow = tid >> 1;
    const int c0 = (tid & 1) * 4;
    const float* gA = A + (size_t)(bm + srow) * K + c0 * 4;
    const float* gB = Wt + (size_t)(bn + srow) * K + c0 * 4;
    uint32_t stA[4], stB[4];
#pragma unroll
    for (int i = 0; i < 4; i++) {
        int c = c0 + i;
        uint32_t off = (uint32_t)srow * 128 + (((uint32_t)(c ^ (srow & 7))) << 4);
        stA[i] = sb + off;
        stB[i] = sb + 16384 + off;
    }

#define LOAD_STAGE(s, t_)                                                  \
    do {                                                                   \
        const float* _a = gA + (t_) * 32;                                  \
        const float* _b = gB + (t_) * 32;                                  \
        uint32_t _so = (uint32_t)(s)*STAGE_BYTES;                          \
        _Pragma("unroll") for (int _i = 0; _i < 4; _i++) {                 \
            cp16(stA[_i] + _so, _a + _i * 4);                              \
            cp16(stB[_i] + _so, _b + _i * 4);                              \
        }                                                                  \
        asm volatile("cp.async.commit_group;");                            \
    } while (0)

    // ---- fragment ldmatrix addresses (per-lane) ----
    // A: tiles {rows m0..m0+7 / +8..+15} x {16B chunk even/odd of the k8 pair}
    int aphase = lane >> 3;                    // 0..3
    int arow7 = lane & 7;
    int arowadd = (aphase & 1) * 8;
    int acbit = aphase >> 1;
    uint32_t aAddr[4];
#pragma unroll
    for (int mf = 0; mf < 4; mf++) {
        int r = wm * 64 + mf * 16 + arow7 + arowadd;
        aAddr[mf] = sb + (uint32_t)r * 128;
    }
    uint32_t aswz[4];
#pragma unroll
    for (int ks = 0; ks < 4; ks++)
        aswz[ks] = ((uint32_t)((2 * ks + acbit) ^ arow7)) << 4;

    // B: x2, lanes 0..15 give addresses (tile0: chunk even, tile1: chunk odd)
    int bl = lane & 15;
    int brow7 = bl & 7;
    int bcbit = bl >> 3;
    uint32_t bAddr[4];
#pragma unroll
    for (int nf = 0; nf < 4; nf++) {
        int r = wn * 32 + nf * 8 + brow7;
        bAddr[nf] = sb + 16384 + (uint32_t)r * 128;
    }
    uint32_t bswz[4];
#pragma unroll
    for (int ks = 0; ks < 4; ks++)
        bswz[ks] = ((uint32_t)((2 * ks + bcbit) ^ brow7)) << 4;

    float acc[4][4][4];
#pragma unroll
    for (int i = 0; i < 4; i++)
#pragma unroll
        for (int j = 0; j < 4; j++)
#pragma unroll
            for (int c = 0; c < 4; c++) acc[i][j][c] = 0.f;

    const int T = K / 32;

    LOAD_STAGE(0, 0);
    LOAD_STAGE(1, 1);

    int s = 0;
    for (int t = 0; t < T; t++) {
        if (t + 1 < T)
            asm volatile("cp.async.wait_group 1;");
        else
            asm volatile("cp.async.wait_group 0;");
        __syncthreads();
        if (t + 2 < T) LOAD_STAGE((s + 2) % STAGES, t + 2);

        uint32_t so = (uint32_t)s * STAGE_BYTES;
#pragma unroll
        for (int ks = 0; ks < 4; ks++) {
            uint32_t af[4][4], bf[4][2];
#pragma unroll
            for (int mf = 0; mf < 4; mf++)
                LDSM_X4(af[mf][0], af[mf][1], af[mf][2], af[mf][3],
                        aAddr[mf] + so + aswz[ks]);
#pragma unroll
            for (int nf = 0; nf < 4; nf++)
                LDSM_X2(bf[nf][0], bf[nf][1], bAddr[nf] + so + bswz[ks]);
#pragma unroll
            for (int mf = 0; mf < 4; mf++)
#pragma unroll
                for (int nf = 0; nf < 4; nf++)
                    MMA_TF32(acc[mf][nf], af[mf], bf[nf]);
        }
        s = (s + 1) % STAGES;
    }

    // ---- epilogue ----
    int r = lane >> 2, kq = lane & 3;
#pragma unroll
    for (int mf = 0; mf < 4; mf++) {
#pragma unroll
        for (int nf = 0; nf < 4; nf++) {
            int n0 = bn + wn * 32 + nf * 8 + kq * 2;
#pragma unroll
            for (int half = 0; half < 2; half++) {
                int m0 = bm + wm * 64 + mf * 16 + r + half * 8;
                float2 v;
                v.x = acc[mf][nf][half * 2 + 0];
                v.y = acc[mf][nf][half * 2 + 1];
                if (flags & FLAG_BIAS) {
                    v.x += bias[n0];
                    v.y += bias[n0 + 1];
                }
                if (flags & FLAG_GELU) {
                    v.x = gelu_tanh(v.x);
                    v.y = gelu_tanh(v.y);
                }
                if (flags & FLAG_RNA) {
                    v.x = rna_tf32(v.x);
                    v.y = rna_tf32(v.y);
                }
                float2* dst = (float2*)&C[(size_t)m0 * Nout + n0];
                if (flags & FLAG_ADD) {
                    float2 old = *dst;
                    v.x += old.x;
                    v.y += old.y;
                }
                *dst = v;
            }
        }
    }
}

// ---------------- flash attention (causal + ALiBi) ---------------------------
__global__ __launch_bounds__(128) void attn_kernel(
    const float* __restrict__ qkv, float* __restrict__ out) {
    __shared__ float Qs[64][65];
    __shared__ float Ks[32][65];
    __shared__ float Vs[32][65];
    __shared__ float Ss[64][33];

    int qt = blockIdx.x;
    int bh = blockIdx.y;
    int b = bh / NH, h = bh % NH;
    int t = threadIdx.x;
    int q = t >> 1;
    int half = t & 1;
    int dstart = half * 32;
    int nq = qt * 64 + q;
    float slope = c_slopes[h];
    const float scale = 0.125f;

    for (int i = 0; i < 32; i++) {
        int idx = t + i * 128;
        int row = idx >> 6, d = idx & 63;
        Qs[row][d] =
            qkv[((size_t)(b * Nn + qt * 64 + row) * (3 * EMB)) + h * DH + d] *
            scale;
    }

    float m = -1e30f, l = 0.f;
    float acc[32];
#pragma unroll
    for (int d = 0; d < 32; d++) acc[d] = 0.f;

    int kt_end = 2 * qt + 1;
    for (int kt = 0; kt <= kt_end; kt++) {
        __syncthreads();
        for (int i = 0; i < 16; i++) {
            int idx = t + i * 128;
            int row = idx >> 6, d = idx & 63;
            size_t base =
                (size_t)(b * Nn + kt * 32 + row) * (3 * EMB) + h * DH + d;
            Ks[row][d] = qkv[base + EMB];
            Vs[row][d] = qkv[base + 2 * EMB];
        }
        __syncthreads();

        for (int jj = 0; jj < 16; jj++) {
            int j = half * 16 + jj;
            int nk = kt * 32 + j;
            float s;
            if (nk > nq) {
                s = -1e30f;
            } else {
                s = 0.f;
#pragma unroll
                for (int d = 0; d < 64; d++) s = fmaf(Qs[q][d], Ks[j][d], s);
                s += slope * (float)nk;
            }
            Ss[q][j] = s;
        }
        __syncthreads();

        float tmax = -1e30f;
#pragma unroll
        for (int j = 0; j < 32; j++) tmax = fmaxf(tmax, Ss[q][j]);
        float newm = fmaxf(m, tmax);
        float corr = expf(m - newm);
        m = newm;
        l *= corr;
#pragma unroll
        for (int d = 0; d < 32; d++) acc[d] *= corr;
        for (int j = 0; j < 32; j++) {
            float p = expf(Ss[q][j] - newm);
            l += p;
#pragma unroll
            for (int d = 0; d < 32; d++)
                acc[d] = fmaf(p, Vs[j][dstart + d], acc[d]);
        }
    }

    float invl = 1.0f / l;
    float* op = out + (size_t)(b * Nn + nq) * EMB + h * DH + dstart;
#pragma unroll
    for (int d = 0; d < 32; d++) op[d] = rna_tf32(acc[d] * invl);
}

// ---------------- host orchestration -----------------------------------------
extern "C" void kernel_launch(void* const* d_in, const int* in_sizes, int n_in,
                              void* d_out, int out_size) {
    const float* x = (const float*)d_in[0];
    const float* wqkv = (const float*)d_in[1];
    const float* bqkv = (const float*)d_in[2];
    const float* wo = (const float*)d_in[3];
    const float* bo = (const float*)d_in[4];
    const float* ln1s = (const float*)d_in[5];
    const float* ln1b = (const float*)d_in[6];
    const float* ln2s = (const float*)d_in[7];
    const float* ln2b = (const float*)d_in[8];
    const float* w1 = (const float*)d_in[9];
    const float* w2 = (const float*)d_in[10];
    const float* lnfs = (const float*)d_in[11];
    const float* lnfb = (const float*)d_in[12];
    float* out = (float*)d_out;

    float *p_h, *p_y, *p_qkv, *p_o, *p_mid;
    float *p_wqkv, *p_wo, *p_w1, *p_w2;
    cudaGetSymbolAddress((void**)&p_h, g_h);
    cudaGetSymbolAddress((void**)&p_y, g_y);
    cudaGetSymbolAddress((void**)&p_qkv, g_qkv);
    cudaGetSymbolAddress((void**)&p_o, g_o);
    cudaGetSymbolAddress((void**)&p_mid, g_mid);
    cudaGetSymbolAddress((void**)&p_wqkv, g_wqkv);
    cudaGetSymbolAddress((void**)&p_wo, g_wo);
    cudaGetSymbolAddress((void**)&p_w1, g_w1);
    cudaGetSymbolAddress((void**)&p_w2, g_w2);

    cudaFuncSetAttribute(gemm_tc, cudaFuncAttributeMaxDynamicSharedMemorySize,
                         GEMM_SMEM);

    copy_kernel<<<(TOK * EMB + 255) / 256, 256>>>(x);

    // transpose + tf32-round all weights: W[K][N] -> Wt[N][K]
    {
        dim3 blk(32, 8);
        transpose_round<<<dim3(3 * EMB / 32, EMB / 32, DEPTH), blk>>>(
            wqkv, p_wqkv, EMB, 3 * EMB);
        transpose_round<<<dim3(EMB / 32, EMB / 32, DEPTH), blk>>>(wo, p_wo,
                                                                  EMB, EMB);
        transpose_round<<<dim3(FF / 32, EMB / 32, DEPTH), blk>>>(w1, p_w1, EMB,
                                                                 FF);
        transpose_round<<<dim3(EMB / 32, FF / 32, DEPTH), blk>>>(w2, p_w2, FF,
                                                                 EMB);
    }

    for (int L = 0; L < DEPTH; L++) {
        ln_kernel<<<TOK, 256>>>(p_h, ln1s + L * EMB, ln1b + L * EMB, p_y, 1);
        {
            dim3 grid(3 * EMB / 128, TOK / 128);
            gemm_tc<<<grid, 256, GEMM_SMEM>>>(
                p_y, p_wqkv + (size_t)L * EMB * 3 * EMB, bqkv + L * 3 * EMB,
                p_qkv, EMB, 3 * EMB, FLAG_BIAS);
        }
        {
            dim3 grid(Nn / 64, Bb * NH);
            attn_kernel<<<grid, 128>>>(p_qkv, p_o);
        }
        {
            dim3 grid(EMB / 128, TOK / 128);
            gemm_tc<<<grid, 256, GEMM_SMEM>>>(p_o, p_wo + (size_t)L * EMB * EMB,
                                              bo + L * EMB, p_h, EMB, EMB,
                                              FLAG_BIAS | FLAG_ADD);
        }
        ln_kernel<<<TOK, 256>>>(p_h, ln2s + L * EMB, ln2b + L * EMB, p_y, 1);
        {
            dim3 grid(FF / 128, TOK / 128);
            gemm_tc<<<grid, 256, GEMM_SMEM>>>(p_y, p_w1 + (size_t)L * EMB * FF,
                                              nullptr, p_mid, EMB, FF,
                                              FLAG_GELU | FLAG_RNA);
        }
        {
            dim3 grid(EMB / 128, TOK / 128);
            gemm_tc<<<grid, 256, GEMM_SMEM>>>(p_mid,
                                              p_w2 + (size_t)L * FF * EMB,
                                              nullptr, p_h, FF, EMB, FLAG_ADD);
        }
    }

    ln_kernel<<<TOK, 256>>>(p_h, lnfs, lnfb, out, 0);
}